// round 15
// baseline (speedup 1.0000x reference)
#include <cuda_runtime.h>
#include <cuda_fp16.h>
#include <cstdint>
#include <cstring>

// ---------------------------------------------------------------------------
// Problem constants
// ---------------------------------------------------------------------------
constexpr int NB   = 8;
constexpr int HH   = 128;
constexpr int HW   = 128 * 128;           // 16384
constexpr int WELEMS = 64 * 64 * 9;       // 36864
constexpr int PAD_H = 8256;               // 16512 B halo (one row + one pixel)

// Scratch (device globals — allocation-free rule). Zero-initialized halos:
// derived corner reads with weight==0 may land there; zeros are finite.
__device__ __half g_xa[PAD_H + NB * HW * 64 + PAD_H];
__device__ __half g_wh[9 * 64 * 64];      // int-valued fp16 weights, SW128-swizzled 8KB/tap
__device__ float  g_scale;

// ---------------------------------------------------------------------------
// Helpers
// ---------------------------------------------------------------------------
__device__ __forceinline__ uint32_t smem_u32(const void* p) {
    uint32_t a;
    asm("{ .reg .u64 t; cvta.to.shared.u64 t, %1; cvt.u32.u64 %0, t; }" : "=r"(a) : "l"(p));
    return a;
}

#define LDSM4(r0, r1, r2, r3, addr)                                           \
    asm volatile("ldmatrix.sync.aligned.m8n8.x4.shared.b16 {%0,%1,%2,%3}, [%4];" \
                 : "=r"(r0), "=r"(r1), "=r"(r2), "=r"(r3) : "r"(addr))

#define MMA16816(d, a0, a1, a2, a3, b0, b1)                                   \
    asm volatile("mma.sync.aligned.m16n8k16.row.col.f32.f16.f16.f32 "         \
                 "{%0,%1,%2,%3},{%4,%5,%6,%7},{%8,%9},{%0,%1,%2,%3};"          \
                 : "+f"((d)[0]), "+f"((d)[1]), "+f"((d)[2]), "+f"((d)[3])      \
                 : "r"(a0), "r"(a1), "r"(a2), "r"(a3), "r"(b0), "r"(b1))

#define CPASYNC16(dst, src)                                                   \
    asm volatile("cp.async.cg.shared.global [%0], [%1], 16;"                  \
                 :: "r"(dst), "l"(src) : "memory")
#define CPASYNC_COMMIT() asm volatile("cp.async.commit_group;" ::: "memory")
#define CPASYNC_WAIT0()  asm volatile("cp.async.wait_group 0;"  ::: "memory")

// ---------------------------------------------------------------------------
// Prologue kernel 1: fused absmax + quantize + relayout (single block)
// ---------------------------------------------------------------------------
__global__ void wquant_kernel(const float* __restrict__ w) {
    __shared__ float red[1024];
    const int t = threadIdx.x;
    const float4* w4 = reinterpret_cast<const float4*>(w);
    float m = 0.f;
    for (int i = t; i < WELEMS / 4; i += 1024) {
        const float4 v = __ldg(w4 + i);
        m = fmaxf(m, fmaxf(fmaxf(fabsf(v.x), fabsf(v.y)), fmaxf(fabsf(v.z), fabsf(v.w))));
    }
    red[t] = m;
    __syncthreads();
    for (int s = 512; s > 0; s >>= 1) {
        if (t < s) red[t] = fmaxf(red[t], red[t + s]);
        __syncthreads();
    }
    const float scale = fmaxf(red[0], 1e-8f) / 127.f;
    if (t == 0) g_scale = scale;
    for (int i = t; i < WELEMS; i += 1024) {
        float q = rintf(w[i] / scale);             // round-half-even = jnp.round
        q = fminf(fmaxf(q, -128.f), 127.f);        // integer, exact in fp16
        const int k = i % 9, ci = (i / 9) % 64, co = i / 576;
        uint32_t off = (uint32_t)(co * 128 + ci * 2);
        off ^= (off >> 3) & 0x70;                  // SW128 swizzle
        g_wh[(k * 8192 + off) >> 1] = __float2half_rn(q);
    }
}

// Prologue kernel 2: x [N,C,H,W] f32 -> NHWC fp16 (vectorized)
__global__ void xcvt_kernel(const float* __restrict__ x) {
    __shared__ float tb[128 * 65];
    const int h = blockIdx.x, n = blockIdx.y, t = threadIdx.x;
    const float* xp = x + (size_t)n * 64 * HW + h * 128;
    for (int i = t; i < 2048; i += 256) {
        const int c = i >> 5, q = i & 31;
        const float4 v = __ldg(reinterpret_cast<const float4*>(xp + c * HW) + q);
        float* tq = tb + (q * 4) * 65 + c;
        tq[0] = v.x; tq[65] = v.y; tq[130] = v.z; tq[195] = v.w;
    }
    __syncthreads();
    __half* op = g_xa + PAD_H + ((size_t)n * 128 + h) * 128 * 64;
    for (int i = t; i < 1024; i += 256) {
        const int wv = i >> 3, cg = i & 7;
        const float* src = tb + wv * 65 + cg * 8;
        const half2 h0 = __floats2half2_rn(src[0], src[1]);
        const half2 h1 = __floats2half2_rn(src[2], src[3]);
        const half2 h2 = __floats2half2_rn(src[4], src[5]);
        const half2 h3 = __floats2half2_rn(src[6], src[7]);
        uint4 o;
        o.x = *reinterpret_cast<const uint32_t*>(&h0);
        o.y = *reinterpret_cast<const uint32_t*>(&h1);
        o.z = *reinterpret_cast<const uint32_t*>(&h2);
        o.w = *reinterpret_cast<const uint32_t*>(&h3);
        *reinterpret_cast<uint4*>(op + wv * 64 + cg * 8) = o;
    }
}

// ---------------------------------------------------------------------------
// Main kernel: one CTA (256 thr) per (ho, n) row; 2 CTAs / SM.
// Full-tap gather (16 LDGs in flight) with MMA halves as latency cover.
// Warp tiling: 32 pix x 32 cout. W tap tiles double-buffered via cp.async.
// ---------------------------------------------------------------------------
constexpr int SMEM_A0   = 0;                     // 16384
constexpr int SMEM_A1   = 16384;                 // 16384
constexpr int SMEM_WB0  = 32768;                 // 8192
constexpr int SMEM_WB1  = 40960;                 // 8192
constexpr int SMEM_POFF = 49152;                 // 1152 * 4B  = 4608
constexpr int SMEM_PWH  = 53760;                 // 1152 * 8B  = 9216
constexpr int SMEM_BYTES = 62976;                // 61.5 KB -> 2 CTAs/SM

__global__ void __launch_bounds__(256, 2)
main_kernel(const float* __restrict__ offset, float* __restrict__ out) {
    extern __shared__ char smem[];
    const uint32_t sb = smem_u32(smem);
    const int t = threadIdx.x;
    const int lane = t & 31, w = t >> 5;
    const int ho = blockIdx.x, n = blockIdx.y;

    const char* whb = reinterpret_cast<const char*>(g_wh);

    // Prefetch W tap 0 into WB0 (32 B per thread)
    CPASYNC16(sb + SMEM_WB0 + t * 32,      whb + t * 32);
    CPASYNC16(sb + SMEM_WB0 + t * 32 + 16, whb + t * 32 + 16);
    CPASYNC_COMMIT();

    // Precompute per-(tap,pixel): clamped base corner offset + 4 masked fp16 weights.
    // Corners derived as off00 + {0, 128, 16384, 16512} bytes; invalid corners have
    // weight 0 and land in halos / neighboring finite data.
    int*   POFF = reinterpret_cast<int*>(smem + SMEM_POFF);
    uint2* PWH  = reinterpret_cast<uint2*>(smem + SMEM_PWH);
    for (int idx = t; idx < 1152; idx += 256) {
        const int k = idx >> 7, p = idx & 127;
        const int ob = ((n * 18 + 2 * k) * 128 + ho) * 128 + p;
        const float oy = __ldg(offset + ob);
        const float ox = __ldg(offset + ob + HW);
        const float py = (float)(ho + k / 3 - 1) + oy;
        const float px = (float)(p + k % 3 - 1) + ox;
        const float fy = floorf(py), fx = floorf(px);
        const float dy = py - fy, dx = px - fx;
        const int y0 = (int)fy, x0 = (int)fx;
        float wv[4];
#pragma unroll
        for (int cn = 0; cn < 4; cn++) {
            const int yy = y0 + (cn >> 1), xx = x0 + (cn & 1);
            float ww = ((cn >> 1) ? dy : 1.f - dy) * ((cn & 1) ? dx : 1.f - dx);
            const bool valid = ((unsigned)yy < 128u) && ((unsigned)xx < 128u);
            wv[cn] = valid ? ww : 0.f;
        }
        const int y0c = min(max(y0, -1), 127), x0c = min(max(x0, -1), 127);
        POFF[idx] = (y0c * 128 + x0c) * 128;           // byte offset (may be negative)
        const half2 wlo = __floats2half2_rn(wv[0], wv[1]);
        const half2 whi = __floats2half2_rn(wv[2], wv[3]);
        uint2 pw;
        pw.x = *reinterpret_cast<const uint32_t*>(&wlo);
        pw.y = *reinterpret_cast<const uint32_t*>(&whi);
        PWH[idx] = pw;
    }
    __syncthreads();

    const char* xbb = reinterpret_cast<const char*>(g_xa + PAD_H)
                    + (size_t)n * (128 * 128 * 128);   // image stride bytes
    const int c = t & 7;                               // 16B chunk within pixel line

    // ldmatrix lane addressing (SW128 xor depends only on row low bits)
    const int lt = lane >> 3, lr = lane & 7;
    const int pgrp = (w & 3) * 32;                     // pixel group of 32
    const int cb   = (w >> 2) * 32;                    // cout group of 32
    const int rsub = (lt & 1) * 8 + lr;                // 0..15
    const uint32_t xrr = (uint32_t)(rsub & 7) << 4;
    const uint32_t cgrp16 = (uint32_t)(lt >> 1) * 16;
    const uint32_t aB0 = (uint32_t)(pgrp + rsub) * 128;
    const uint32_t aB1 = aB0 + 16 * 128;
    const uint32_t bB0 = (uint32_t)(cb + rsub) * 128;
    const uint32_t bB1 = bB0 + 16 * 128;

    float acc[2][4][4];
#pragma unroll
    for (int i = 0; i < 2; i++)
#pragma unroll
        for (int j = 0; j < 4; j++)
#pragma unroll
            for (int q = 0; q < 4; q++) acc[i][j][q] = 0.f;

    uint4 v[4][4];          // FULL tap in flight: 16 LDG.128 (64 regs)

    auto gather_full = [&](int k) {
        const int pbase = k << 7;
#pragma unroll
        for (int a = 0; a < 4; a++) {
            const int p = ((a * 256 + t) >> 3);
            const int o0 = POFF[pbase + p] + c * 16;
            v[a][0] = *reinterpret_cast<const uint4*>(xbb + o0);
            v[a][1] = *reinterpret_cast<const uint4*>(xbb + o0 + 128);
            v[a][2] = *reinterpret_cast<const uint4*>(xbb + o0 + 16384);
            v[a][3] = *reinterpret_cast<const uint4*>(xbb + o0 + 16512);
        }
    };

    // consume v[2h], v[2h+1]
    auto bilinear_half = [&](char* abufp, int k, int h) {
#pragma unroll
        for (int a = 2 * h; a < 2 * h + 2; a++) {
            const int p = ((a * 256 + t) >> 3);
            const uint2 pw = PWH[(k << 7) + p];
            const half2 wlo = *reinterpret_cast<const half2*>(&pw.x);
            const half2 whi = *reinterpret_cast<const half2*>(&pw.y);
            const half2 w00 = __low2half2(wlo),  w01 = __high2half2(wlo);
            const half2 w10 = __low2half2(whi),  w11 = __high2half2(whi);
            const half2* q0 = reinterpret_cast<const half2*>(&v[a][0]);
            const half2* q1 = reinterpret_cast<const half2*>(&v[a][1]);
            const half2* q2 = reinterpret_cast<const half2*>(&v[a][2]);
            const half2* q3 = reinterpret_cast<const half2*>(&v[a][3]);
            half2 s[4];
#pragma unroll
            for (int j = 0; j < 4; j++) {
                s[j] = __hmul2(w00, q0[j]);
                s[j] = __hfma2(w01, q1[j], s[j]);
                s[j] = __hfma2(w10, q2[j], s[j]);
                s[j] = __hfma2(w11, q3[j], s[j]);
            }
            uint32_t boff = (uint32_t)(p * 128 + c * 16);
            boff ^= (boff >> 3) & 0x70;
            uint4 ov;
            ov.x = *reinterpret_cast<const uint32_t*>(&s[0]);
            ov.y = *reinterpret_cast<const uint32_t*>(&s[1]);
            ov.z = *reinterpret_cast<const uint32_t*>(&s[2]);
            ov.w = *reinterpret_cast<const uint32_t*>(&s[3]);
            *reinterpret_cast<uint4*>(abufp + boff) = ov;
        }
    };

    // Half of the tap GEMM: kc = 2*h, 2*h+1
    auto mma_half = [&](uint32_t abuf, uint32_t wk, int h) {
#pragma unroll
        for (int kk = 0; kk < 2; kk++) {
            const int kc = 2 * h + kk;
            const uint32_t bx = ((uint32_t)(kc * 32) + cgrp16) ^ xrr;
            uint32_t a0[4], a1[4];
            LDSM4(a0[0], a0[1], a0[2], a0[3], abuf + aB0 + bx);
            LDSM4(a1[0], a1[1], a1[2], a1[3], abuf + aB1 + bx);
#pragma unroll
            for (int nh = 0; nh < 2; nh++) {
                uint32_t b0, b1, b2, b3;
                LDSM4(b0, b1, b2, b3, wk + (nh ? bB1 : bB0) + bx);
                MMA16816(acc[0][nh * 2],     a0[0], a0[1], a0[2], a0[3], b0, b2);
                MMA16816(acc[0][nh * 2 + 1], a0[0], a0[1], a0[2], a0[3], b1, b3);
                MMA16816(acc[1][nh * 2],     a1[0], a1[1], a1[2], a1[3], b0, b2);
                MMA16816(acc[1][nh * 2 + 1], a1[0], a1[1], a1[2], a1[3], b1, b3);
            }
        }
    };

    // Pipeline prologue: fill A buffer 0 with tap 0
    gather_full(0);
    bilinear_half(smem + SMEM_A0, 0, 0);
    bilinear_half(smem + SMEM_A0, 0, 1);
    CPASYNC_WAIT0();            // W tap 0 copies done (thread-local)
    __syncthreads();            // ...and published CTA-wide

#pragma unroll 1
    for (int k = 0; k < 9; k++) {
        const uint32_t wk   = sb + ((k & 1) ? SMEM_WB1 : SMEM_WB0);
        const uint32_t abuf = sb + ((k & 1) ? SMEM_A1 : SMEM_A0);
        char* anext = smem + (((k + 1) & 1) ? SMEM_A1 : SMEM_A0);
        if (k < 8) {
            // stage W(k+1) under this tap
            const uint32_t wdst = sb + (((k + 1) & 1) ? SMEM_WB1 : SMEM_WB0) + t * 32;
            const char* wsrc = whb + (k + 1) * 8192 + t * 32;
            CPASYNC16(wdst, wsrc);
            CPASYNC16(wdst + 16, wsrc + 16);
            CPASYNC_COMMIT();
            gather_full(k + 1);              // all 16 LDGs in flight (MLP=16)
            mma_half(abuf, wk, 0);           // cover for v[0..1]
            bilinear_half(anext, k + 1, 0);
            mma_half(abuf, wk, 1);           // extra cover for v[2..3]
            bilinear_half(anext, k + 1, 1);
            CPASYNC_WAIT0();                 // W(k+1) done before publishing barrier
        } else {
            mma_half(abuf, wk, 0);
            mma_half(abuf, wk, 1);
        }
        __syncthreads();
    }

    // ---- epilogue: scale, transpose through smem, coalesced float4 stores ----
    const float scale = g_scale;
    float* EPI = reinterpret_cast<float*>(smem);      // [64 cout][pitch 132] = 33792 B
    const int gr = lane >> 2, ci2 = (lane & 3) * 2;
#pragma unroll
    for (int mt = 0; mt < 2; mt++)
#pragma unroll
        for (int nt = 0; nt < 4; nt++) {
            const int pix = pgrp + mt * 16 + gr;
            const int co  = cb + nt * 8 + ci2;
            EPI[co * 132 + pix]           = acc[mt][nt][0] * scale;
            EPI[(co + 1) * 132 + pix]     = acc[mt][nt][1] * scale;
            EPI[co * 132 + pix + 8]       = acc[mt][nt][2] * scale;
            EPI[(co + 1) * 132 + pix + 8] = acc[mt][nt][3] * scale;
        }
    __syncthreads();
    float* op = out + (size_t)n * 64 * HW + ho * 128;
#pragma unroll
    for (int r = 0; r < 8; r++) {
        const int idx = r * 256 + t;                  // 2048 float4 = 64 couts x 32
        const int co = idx >> 5, p4 = (idx & 31) * 4;
        const float4 vv = *reinterpret_cast<const float4*>(EPI + co * 132 + p4);
        *reinterpret_cast<float4*>(op + co * HW + p4) = vv;
    }
}

// ---------------------------------------------------------------------------
extern "C" void kernel_launch(void* const* d_in, const int* in_sizes, int n_in,
                              void* d_out, int out_size) {
    const float* x      = (const float*)d_in[0];
    const float* offset = (const float*)d_in[1];
    const float* weight = (const float*)d_in[2];
    float* out = (float*)d_out;

    cudaFuncSetAttribute(main_kernel, cudaFuncAttributeMaxDynamicSharedMemorySize,
                         SMEM_BYTES);

    wquant_kernel<<<1, 1024>>>(weight);
    xcvt_kernel<<<dim3(HH, NB), 256>>>(x);
    main_kernel<<<dim3(HH, NB), 256, SMEM_BYTES>>>(offset, out);
}

// round 17
// speedup vs baseline: 1.1384x; 1.1384x over previous
#include <cuda_runtime.h>
#include <cuda_fp16.h>
#include <cstdint>
#include <cstring>

// ---------------------------------------------------------------------------
// Problem constants
// ---------------------------------------------------------------------------
constexpr int NB   = 8;
constexpr int HH   = 128;
constexpr int HW   = 128 * 128;           // 16384
constexpr int WELEMS = 64 * 64 * 9;       // 36864
constexpr int PAD_H = 8256;               // 16512 B halo (one row + one pixel)

// Scratch (device globals — allocation-free rule). Zero-initialized halos:
// derived corner reads with weight==0 may land there; zeros are finite.
__device__ __half g_xa[PAD_H + NB * HW * 64 + PAD_H];
__device__ __half g_wh[9 * 64 * 64];      // int-valued fp16 weights, SW128-swizzled 8KB/tap
__device__ float  g_scale;

// ---------------------------------------------------------------------------
// Helpers
// ---------------------------------------------------------------------------
__device__ __forceinline__ uint32_t smem_u32(const void* p) {
    uint32_t a;
    asm("{ .reg .u64 t; cvta.to.shared.u64 t, %1; cvt.u32.u64 %0, t; }" : "=r"(a) : "l"(p));
    return a;
}

#define LDSM4(r0, r1, r2, r3, addr)                                           \
    asm volatile("ldmatrix.sync.aligned.m8n8.x4.shared.b16 {%0,%1,%2,%3}, [%4];" \
                 : "=r"(r0), "=r"(r1), "=r"(r2), "=r"(r3) : "r"(addr))

#define MMA16816(d, a0, a1, a2, a3, b0, b1)                                   \
    asm volatile("mma.sync.aligned.m16n8k16.row.col.f32.f16.f16.f32 "         \
                 "{%0,%1,%2,%3},{%4,%5,%6,%7},{%8,%9},{%0,%1,%2,%3};"          \
                 : "+f"((d)[0]), "+f"((d)[1]), "+f"((d)[2]), "+f"((d)[3])      \
                 : "r"(a0), "r"(a1), "r"(a2), "r"(a3), "r"(b0), "r"(b1))

#define CPASYNC16(dst, src)                                                   \
    asm volatile("cp.async.cg.shared.global [%0], [%1], 16;"                  \
                 :: "r"(dst), "l"(src) : "memory")
#define CPASYNC_COMMIT() asm volatile("cp.async.commit_group;" ::: "memory")
#define CPASYNC_WAIT0()  asm volatile("cp.async.wait_group 0;"  ::: "memory")

// ---------------------------------------------------------------------------
// Prologue kernel 1: absmax -> scale (single block, one pass)
// ---------------------------------------------------------------------------
__global__ void absmax_kernel(const float* __restrict__ w) {
    __shared__ float red[1024];
    const int t = threadIdx.x;
    const float4* w4 = reinterpret_cast<const float4*>(w);
    float m = 0.f;
    for (int i = t; i < WELEMS / 4; i += 1024) {
        const float4 v = __ldg(w4 + i);
        m = fmaxf(m, fmaxf(fmaxf(fabsf(v.x), fabsf(v.y)), fmaxf(fabsf(v.z), fabsf(v.w))));
    }
    red[t] = m;
    __syncthreads();
    for (int s = 512; s > 0; s >>= 1) {
        if (t < s) red[t] = fmaxf(red[t], red[t + s]);
        __syncthreads();
    }
    if (t == 0) g_scale = fmaxf(red[0], 1e-8f) / 127.f;
}

// Prologue kernel 2: quantize + relayout (parallel, SW128-swizzled, [k][cout][cin])
__global__ void wconv_kernel(const float* __restrict__ w) {
    const float scale = g_scale;
    const int i = blockIdx.x * 256 + threadIdx.x;
    if (i >= WELEMS) return;
    float q = rintf(w[i] / scale);                 // round-half-even = jnp.round
    q = fminf(fmaxf(q, -128.f), 127.f);            // integer, exact in fp16
    const int k = i % 9, ci = (i / 9) % 64, co = i / 576;
    uint32_t off = (uint32_t)(co * 128 + ci * 2);
    off ^= (off >> 3) & 0x70;                      // SW128 swizzle
    g_wh[(k * 8192 + off) >> 1] = __float2half_rn(q);
}

// Prologue kernel 3: x [N,C,H,W] f32 -> NHWC fp16 (vectorized)
__global__ void xcvt_kernel(const float* __restrict__ x) {
    __shared__ float tb[128 * 65];
    const int h = blockIdx.x, n = blockIdx.y, t = threadIdx.x;
    const float* xp = x + (size_t)n * 64 * HW + h * 128;
    for (int i = t; i < 2048; i += 256) {
        const int c = i >> 5, q = i & 31;
        const float4 v = __ldg(reinterpret_cast<const float4*>(xp + c * HW) + q);
        float* tq = tb + (q * 4) * 65 + c;
        tq[0] = v.x; tq[65] = v.y; tq[130] = v.z; tq[195] = v.w;
    }
    __syncthreads();
    __half* op = g_xa + PAD_H + ((size_t)n * 128 + h) * 128 * 64;
    for (int i = t; i < 1024; i += 256) {
        const int wv = i >> 3, cg = i & 7;
        const float* src = tb + wv * 65 + cg * 8;
        const half2 h0 = __floats2half2_rn(src[0], src[1]);
        const half2 h1 = __floats2half2_rn(src[2], src[3]);
        const half2 h2 = __floats2half2_rn(src[4], src[5]);
        const half2 h3 = __floats2half2_rn(src[6], src[7]);
        uint4 o;
        o.x = *reinterpret_cast<const uint32_t*>(&h0);
        o.y = *reinterpret_cast<const uint32_t*>(&h1);
        o.z = *reinterpret_cast<const uint32_t*>(&h2);
        o.w = *reinterpret_cast<const uint32_t*>(&h3);
        *reinterpret_cast<uint4*>(op + wv * 64 + cg * 8) = o;
    }
}

// ---------------------------------------------------------------------------
// Main kernel: one CTA (256 thr) per (ho, n) row; 2 CTAs / SM.
// Full-tap gather (16 LDGs in flight) with MMA halves as latency cover.
// Warp tiling: 32 pix x 32 cout. W tap tiles double-buffered via cp.async.
// ---------------------------------------------------------------------------
constexpr int SMEM_A0   = 0;                     // 16384
constexpr int SMEM_A1   = 16384;                 // 16384
constexpr int SMEM_WB0  = 32768;                 // 8192
constexpr int SMEM_WB1  = 40960;                 // 8192
constexpr int SMEM_POFF = 49152;                 // 1152 * 4B  = 4608
constexpr int SMEM_PWH  = 53760;                 // 1152 * 8B  = 9216
constexpr int SMEM_BYTES = 62976;                // 61.5 KB -> 2 CTAs/SM

__global__ void __launch_bounds__(256, 2)
main_kernel(const float* __restrict__ offset, float* __restrict__ out) {
    extern __shared__ char smem[];
    const uint32_t sb = smem_u32(smem);
    const int t = threadIdx.x;
    const int lane = t & 31, w = t >> 5;
    const int ho = blockIdx.x, n = blockIdx.y;

    const char* whb = reinterpret_cast<const char*>(g_wh);

    // Prefetch W tap 0 into WB0 (32 B per thread)
    CPASYNC16(sb + SMEM_WB0 + t * 32,      whb + t * 32);
    CPASYNC16(sb + SMEM_WB0 + t * 32 + 16, whb + t * 32 + 16);
    CPASYNC_COMMIT();

    // Precompute per-(tap,pixel): clamped base corner offset + 4 masked fp16 weights.
    // Corners derived as off00 + {0, 128, 16384, 16512} bytes; invalid corners have
    // weight 0 and land in halos / neighboring finite data.
    int*   POFF = reinterpret_cast<int*>(smem + SMEM_POFF);
    uint2* PWH  = reinterpret_cast<uint2*>(smem + SMEM_PWH);
    for (int idx = t; idx < 1152; idx += 256) {
        const int k = idx >> 7, p = idx & 127;
        const int ob = ((n * 18 + 2 * k) * 128 + ho) * 128 + p;
        const float oy = __ldg(offset + ob);
        const float ox = __ldg(offset + ob + HW);
        const float py = (float)(ho + k / 3 - 1) + oy;
        const float px = (float)(p + k % 3 - 1) + ox;
        const float fy = floorf(py), fx = floorf(px);
        const float dy = py - fy, dx = px - fx;
        const int y0 = (int)fy, x0 = (int)fx;
        float wv[4];
#pragma unroll
        for (int cn = 0; cn < 4; cn++) {
            const int yy = y0 + (cn >> 1), xx = x0 + (cn & 1);
            float ww = ((cn >> 1) ? dy : 1.f - dy) * ((cn & 1) ? dx : 1.f - dx);
            const bool valid = ((unsigned)yy < 128u) && ((unsigned)xx < 128u);
            wv[cn] = valid ? ww : 0.f;
        }
        const int y0c = min(max(y0, -1), 127), x0c = min(max(x0, -1), 127);
        POFF[idx] = (y0c * 128 + x0c) * 128;           // byte offset (may be negative)
        const half2 wlo = __floats2half2_rn(wv[0], wv[1]);
        const half2 whi = __floats2half2_rn(wv[2], wv[3]);
        uint2 pw;
        pw.x = *reinterpret_cast<const uint32_t*>(&wlo);
        pw.y = *reinterpret_cast<const uint32_t*>(&whi);
        PWH[idx] = pw;
    }
    __syncthreads();

    const char* xbb = reinterpret_cast<const char*>(g_xa + PAD_H)
                    + (size_t)n * (128 * 128 * 128);   // image stride bytes
    const int c = t & 7;                               // 16B chunk within pixel line

    // ldmatrix lane addressing (SW128 xor depends only on row low bits)
    const int lt = lane >> 3, lr = lane & 7;
    const int pgrp = (w & 3) * 32;                     // pixel group of 32
    const int cb   = (w >> 2) * 32;                    // cout group of 32
    const int rsub = (lt & 1) * 8 + lr;                // 0..15
    const uint32_t xrr = (uint32_t)(rsub & 7) << 4;
    const uint32_t cgrp16 = (uint32_t)(lt >> 1) * 16;
    const uint32_t aB0 = (uint32_t)(pgrp + rsub) * 128;
    const uint32_t aB1 = aB0 + 16 * 128;
    const uint32_t bB0 = (uint32_t)(cb + rsub) * 128;
    const uint32_t bB1 = bB0 + 16 * 128;

    float acc[2][4][4];
#pragma unroll
    for (int i = 0; i < 2; i++)
#pragma unroll
        for (int j = 0; j < 4; j++)
#pragma unroll
            for (int q = 0; q < 4; q++) acc[i][j][q] = 0.f;

    uint4 v[4][4];          // FULL tap in flight: 16 LDG.128 (64 regs)

    auto gather_full = [&](int k) {
        const int pbase = k << 7;
#pragma unroll
        for (int a = 0; a < 4; a++) {
            const int p = ((a * 256 + t) >> 3);
            const int o0 = POFF[pbase + p] + c * 16;
            v[a][0] = *reinterpret_cast<const uint4*>(xbb + o0);
            v[a][1] = *reinterpret_cast<const uint4*>(xbb + o0 + 128);
            v[a][2] = *reinterpret_cast<const uint4*>(xbb + o0 + 16384);
            v[a][3] = *reinterpret_cast<const uint4*>(xbb + o0 + 16512);
        }
    };

    // consume v[2h], v[2h+1]
    auto bilinear_half = [&](char* abufp, int k, int h) {
#pragma unroll
        for (int a = 2 * h; a < 2 * h + 2; a++) {
            const int p = ((a * 256 + t) >> 3);
            const uint2 pw = PWH[(k << 7) + p];
            const half2 wlo = *reinterpret_cast<const half2*>(&pw.x);
            const half2 whi = *reinterpret_cast<const half2*>(&pw.y);
            const half2 w00 = __low2half2(wlo),  w01 = __high2half2(wlo);
            const half2 w10 = __low2half2(whi),  w11 = __high2half2(whi);
            const half2* q0 = reinterpret_cast<const half2*>(&v[a][0]);
            const half2* q1 = reinterpret_cast<const half2*>(&v[a][1]);
            const half2* q2 = reinterpret_cast<const half2*>(&v[a][2]);
            const half2* q3 = reinterpret_cast<const half2*>(&v[a][3]);
            half2 s[4];
#pragma unroll
            for (int j = 0; j < 4; j++) {
                s[j] = __hmul2(w00, q0[j]);
                s[j] = __hfma2(w01, q1[j], s[j]);
                s[j] = __hfma2(w10, q2[j], s[j]);
                s[j] = __hfma2(w11, q3[j], s[j]);
            }
            uint32_t boff = (uint32_t)(p * 128 + c * 16);
            boff ^= (boff >> 3) & 0x70;
            uint4 ov;
            ov.x = *reinterpret_cast<const uint32_t*>(&s[0]);
            ov.y = *reinterpret_cast<const uint32_t*>(&s[1]);
            ov.z = *reinterpret_cast<const uint32_t*>(&s[2]);
            ov.w = *reinterpret_cast<const uint32_t*>(&s[3]);
            *reinterpret_cast<uint4*>(abufp + boff) = ov;
        }
    };

    // Half of the tap GEMM: kc = 2*h, 2*h+1
    auto mma_half = [&](uint32_t abuf, uint32_t wk, int h) {
#pragma unroll
        for (int kk = 0; kk < 2; kk++) {
            const int kc = 2 * h + kk;
            const uint32_t bx = ((uint32_t)(kc * 32) + cgrp16) ^ xrr;
            uint32_t a0[4], a1[4];
            LDSM4(a0[0], a0[1], a0[2], a0[3], abuf + aB0 + bx);
            LDSM4(a1[0], a1[1], a1[2], a1[3], abuf + aB1 + bx);
#pragma unroll
            for (int nh = 0; nh < 2; nh++) {
                uint32_t b0, b1, b2, b3;
                LDSM4(b0, b1, b2, b3, wk + (nh ? bB1 : bB0) + bx);
                MMA16816(acc[0][nh * 2],     a0[0], a0[1], a0[2], a0[3], b0, b2);
                MMA16816(acc[0][nh * 2 + 1], a0[0], a0[1], a0[2], a0[3], b1, b3);
                MMA16816(acc[1][nh * 2],     a1[0], a1[1], a1[2], a1[3], b0, b2);
                MMA16816(acc[1][nh * 2 + 1], a1[0], a1[1], a1[2], a1[3], b1, b3);
            }
        }
    };

    // Pipeline prologue: fill A buffer 0 with tap 0
    gather_full(0);
    bilinear_half(smem + SMEM_A0, 0, 0);
    bilinear_half(smem + SMEM_A0, 0, 1);
    CPASYNC_WAIT0();            // W tap 0 copies done (thread-local)
    __syncthreads();            // ...and published CTA-wide

#pragma unroll 1
    for (int k = 0; k < 9; k++) {
        const uint32_t wk   = sb + ((k & 1) ? SMEM_WB1 : SMEM_WB0);
        const uint32_t abuf = sb + ((k & 1) ? SMEM_A1 : SMEM_A0);
        char* anext = smem + (((k + 1) & 1) ? SMEM_A1 : SMEM_A0);
        if (k < 8) {
            // stage W(k+1) under this tap
            const uint32_t wdst = sb + (((k + 1) & 1) ? SMEM_WB1 : SMEM_WB0) + t * 32;
            const char* wsrc = whb + (k + 1) * 8192 + t * 32;
            CPASYNC16(wdst, wsrc);
            CPASYNC16(wdst + 16, wsrc + 16);
            CPASYNC_COMMIT();
            gather_full(k + 1);              // all 16 LDGs in flight (MLP=16)
            mma_half(abuf, wk, 0);           // cover for v[0..1]
            bilinear_half(anext, k + 1, 0);
            mma_half(abuf, wk, 1);           // extra cover for v[2..3]
            bilinear_half(anext, k + 1, 1);
            CPASYNC_WAIT0();                 // W(k+1) done before publishing barrier
        } else {
            mma_half(abuf, wk, 0);
            mma_half(abuf, wk, 1);
        }
        __syncthreads();
    }

    // ---- epilogue: scale, transpose through smem, coalesced float4 stores ----
    const float scale = g_scale;
    float* EPI = reinterpret_cast<float*>(smem);      // [64 cout][pitch 132] = 33792 B
    const int gr = lane >> 2, ci2 = (lane & 3) * 2;
#pragma unroll
    for (int mt = 0; mt < 2; mt++)
#pragma unroll
        for (int nt = 0; nt < 4; nt++) {
            const int pix = pgrp + mt * 16 + gr;
            const int co  = cb + nt * 8 + ci2;
            EPI[co * 132 + pix]           = acc[mt][nt][0] * scale;
            EPI[(co + 1) * 132 + pix]     = acc[mt][nt][1] * scale;
            EPI[co * 132 + pix + 8]       = acc[mt][nt][2] * scale;
            EPI[(co + 1) * 132 + pix + 8] = acc[mt][nt][3] * scale;
        }
    __syncthreads();
    float* op = out + (size_t)n * 64 * HW + ho * 128;
#pragma unroll
    for (int r = 0; r < 8; r++) {
        const int idx = r * 256 + t;                  // 2048 float4 = 64 couts x 32
        const int co = idx >> 5, p4 = (idx & 31) * 4;
        const float4 vv = *reinterpret_cast<const float4*>(EPI + co * 132 + p4);
        *reinterpret_cast<float4*>(op + co * HW + p4) = vv;
    }
}

// ---------------------------------------------------------------------------
extern "C" void kernel_launch(void* const* d_in, const int* in_sizes, int n_in,
                              void* d_out, int out_size) {
    const float* x      = (const float*)d_in[0];
    const float* offset = (const float*)d_in[1];
    const float* weight = (const float*)d_in[2];
    float* out = (float*)d_out;

    cudaFuncSetAttribute(main_kernel, cudaFuncAttributeMaxDynamicSharedMemorySize,
                         SMEM_BYTES);

    absmax_kernel<<<1, 1024>>>(weight);
    wconv_kernel<<<(WELEMS + 255) / 256, 256>>>(weight);
    xcvt_kernel<<<dim3(HH, NB), 256>>>(x);
    main_kernel<<<dim3(HH, NB), 256, SMEM_BYTES>>>(offset, out);
}